// round 1
// baseline (speedup 1.0000x reference)
#include <cuda_runtime.h>

// Chamfer distance, B=2, N=8192, 3D points.
// dist(i,j)^2 = ||q_i||^2 + 2*(0.5*||p_j||^2 - q_i . p_j)
// Per direction minimize h_j = 0.5*||p_j||^2 - q_i . p_j  (3 FMA + 1 FMNMX per pair).
// sqrt applied only after the min (monotonic).

#define BATCH   2
#define NPTS    8192
#define THREADS 256
#define ITILE   8
#define QBLK    (THREADS * ITILE)   // 2048 queries per CTA
#define NQBLK   (NPTS / QBLK)       // 4
#define JCHUNKS 16
#define JCHUNK  (NPTS / JCHUNKS)    // 512 refs per chunk

// Scratch: partial min squared distance per (dir*B+b, chunk, query). 4 MB.
__device__ float g_partial[2 * BATCH * JCHUNKS * NPTS];
__device__ float g_blocksum[64];

__global__ __launch_bounds__(THREADS)
void chamfer_pass(const float* __restrict__ pred, const float* __restrict__ gt) {
    const int chunk  = blockIdx.x;          // 0..JCHUNKS-1
    const int qblock = blockIdx.y;          // 0..NQBLK-1
    const int bz     = blockIdx.z;          // dir*BATCH + b, 0..3
    const int dir    = bz >> 1;
    const int b      = bz & 1;

    // dir 0: queries = gt, refs = pred  (dist1: per-gt nearest pred)
    // dir 1: queries = pred, refs = gt  (dist2: per-pred nearest gt)
    const float* __restrict__ qarr = dir ? pred : gt;
    const float* __restrict__ rarr = dir ? gt   : pred;

    __shared__ float4 sp[JCHUNK];

    // Stage this chunk's reference points into shared: (x, y, z, 0.5*|p|^2)
    const int jbase = chunk * JCHUNK;
    for (int t = threadIdx.x; t < JCHUNK; t += THREADS) {
        const float* r = rarr + ((size_t)b * NPTS + jbase + t) * 3;
        float x = r[0], y = r[1], z = r[2];
        sp[t] = make_float4(x, y, z, 0.5f * (x * x + y * y + z * z));
    }

    // Each thread owns ITILE queries (negated coords for pure-FMA inner loop).
    float nx[ITILE], ny[ITILE], nz[ITILE], qs[ITILE], m[ITILE];
    const int q0 = qblock * QBLK + threadIdx.x;
#pragma unroll
    for (int k = 0; k < ITILE; k++) {
        const float* g = qarr + ((size_t)b * NPTS + q0 + k * THREADS) * 3;
        float x = g[0], y = g[1], z = g[2];
        nx[k] = -x; ny[k] = -y; nz[k] = -z;
        qs[k] = x * x + y * y + z * z;
        m[k]  = 3.4e38f;
    }
    __syncthreads();

#pragma unroll 4
    for (int j = 0; j < JCHUNK; j++) {
        float4 p = sp[j];   // broadcast, conflict-free
#pragma unroll
        for (int k = 0; k < ITILE; k++) {
            float h = fmaf(nx[k], p.x, fmaf(ny[k], p.y, fmaf(nz[k], p.z, p.w)));
            m[k] = fminf(m[k], h);
        }
    }

    float* out = g_partial + ((size_t)bz * JCHUNKS + chunk) * NPTS;
#pragma unroll
    for (int k = 0; k < ITILE; k++) {
        // squared distance, clamped at 0 (clamp commutes with the later min)
        float sq = fmaxf(fmaf(2.0f, m[k], qs[k]), 0.0f);
        out[q0 + k * THREADS] = sq;
    }
}

// Stage 1: min over chunks, sqrt, per-block sum. 64 blocks x 256 threads,
// 2 queries per thread covers 2*BATCH*NPTS = 32768 query slots.
__global__ __launch_bounds__(THREADS)
void chamfer_reduce_a() {
    __shared__ float ssum[THREADS];
    float acc = 0.0f;
#pragma unroll
    for (int r = 0; r < 2; r++) {
        int f  = blockIdx.x * 512 + r * THREADS + threadIdx.x;  // 0..32767
        int db = f / NPTS;   // dir*BATCH + b
        int q  = f % NPTS;
        const float* p = g_partial + (size_t)db * JCHUNKS * NPTS + q;
        float mv = 3.4e38f;
#pragma unroll
        for (int c = 0; c < JCHUNKS; c++) mv = fminf(mv, p[(size_t)c * NPTS]);
        acc += sqrtf(mv);
    }
    ssum[threadIdx.x] = acc;
    __syncthreads();
    for (int s = THREADS / 2; s > 0; s >>= 1) {
        if (threadIdx.x < s) ssum[threadIdx.x] += ssum[threadIdx.x + s];
        __syncthreads();
    }
    if (threadIdx.x == 0) g_blocksum[blockIdx.x] = ssum[0];
}

// Stage 2: final deterministic sum of the 64 block sums.
__global__ void chamfer_reduce_b(float* __restrict__ out) {
    __shared__ float s[64];
    s[threadIdx.x] = g_blocksum[threadIdx.x];
    __syncthreads();
    for (int st = 32; st > 0; st >>= 1) {
        if (threadIdx.x < st) s[threadIdx.x] += s[threadIdx.x + st];
        __syncthreads();
    }
    if (threadIdx.x == 0) out[0] = s[0] / (float)(BATCH * NPTS);
}

extern "C" void kernel_launch(void* const* d_in, const int* in_sizes, int n_in,
                              void* d_out, int out_size) {
    const float* pred = (const float*)d_in[0];
    const float* gt   = (const float*)d_in[1];
    float* out        = (float*)d_out;

    dim3 grid(JCHUNKS, NQBLK, 2 * BATCH);   // 16 x 4 x 4 = 256 CTAs
    chamfer_pass<<<grid, THREADS>>>(pred, gt);
    chamfer_reduce_a<<<64, THREADS>>>();
    chamfer_reduce_b<<<1, 64>>>(out);
}

// round 2
// speedup vs baseline: 1.1166x; 1.1166x over previous
#include <cuda_runtime.h>

// Chamfer distance, B=2, N=8192, 3D points.
// Per direction minimize h_j = 0.5*||p_j||^2 - q_i . p_j, sqrt after the min.
// Inner loop uses packed fma.rn.f32x2 (Blackwell FFMA2): 2 reference points
// per instruction -> 3 FFMA2 + 2 FMNMX per 2 pairs.

#define BATCH   2
#define NPTS    8192
#define THREADS 256
#define ITILE   4
#define QBLK    (THREADS * ITILE)   // 1024 queries per CTA
#define NQBLK   (NPTS / QBLK)       // 8
#define JCHUNKS 32
#define JCHUNK  (NPTS / JCHUNKS)    // 256 refs per chunk
#define JPAIRS  (JCHUNK / 2)        // 128

// Scratch: partial min squared distance per (dir*B+b, chunk, query). 4 MB.
__device__ float g_partial[2 * BATCH * JCHUNKS * NPTS];
__device__ float g_blocksum[64];

typedef unsigned long long u64;

__device__ __forceinline__ u64 pack2(float lo, float hi) {
    u64 d; asm("mov.b64 %0, {%1,%2};" : "=l"(d) : "f"(lo), "f"(hi)); return d;
}
__device__ __forceinline__ void unpack2(u64 d, float& lo, float& hi) {
    asm("mov.b64 {%0,%1}, %2;" : "=f"(lo), "=f"(hi) : "l"(d));
}
__device__ __forceinline__ u64 fma2(u64 a, u64 b, u64 c) {
    u64 d; asm("fma.rn.f32x2 %0, %1, %2, %3;" : "=l"(d) : "l"(a), "l"(b), "l"(c));
    return d;
}

__global__ __launch_bounds__(THREADS)
void chamfer_pass(const float* __restrict__ pred, const float* __restrict__ gt) {
    const int chunk  = blockIdx.x;          // 0..JCHUNKS-1
    const int qblock = blockIdx.y;          // 0..NQBLK-1
    const int bz     = blockIdx.z;          // dir*BATCH + b, 0..3
    const int dir    = bz >> 1;
    const int b      = bz & 1;

    // dir 0: queries = gt, refs = pred; dir 1: queries = pred, refs = gt
    const float* __restrict__ qarr = dir ? pred : gt;
    const float* __restrict__ rarr = dir ? gt   : pred;

    // Pair-packed reference staging: sxy[jp] = {x0,x1,y0,y1}, szc[jp] = {z0,z1,c0,c1}
    __shared__ float4 sxy[JPAIRS];
    __shared__ float4 szc[JPAIRS];

    const int jbase = chunk * JCHUNK;
    for (int jp = threadIdx.x; jp < JPAIRS; jp += THREADS) {
        const float* r = rarr + ((size_t)b * NPTS + jbase + 2 * jp) * 3;
        float x0 = r[0], y0 = r[1], z0 = r[2];
        float x1 = r[3], y1 = r[4], z1 = r[5];
        float c0 = 0.5f * (x0 * x0 + y0 * y0 + z0 * z0);
        float c1 = 0.5f * (x1 * x1 + y1 * y1 + z1 * z1);
        sxy[jp] = make_float4(x0, x1, y0, y1);
        szc[jp] = make_float4(z0, z1, c0, c1);
    }

    // Per-thread queries: negated coords replicated into both f32x2 halves.
    u64 nx2[ITILE], ny2[ITILE], nz2[ITILE];
    float qs[ITILE], mA[ITILE], mB[ITILE];
    const int q0 = qblock * QBLK + threadIdx.x;
#pragma unroll
    for (int k = 0; k < ITILE; k++) {
        const float* g = qarr + ((size_t)b * NPTS + q0 + k * THREADS) * 3;
        float x = g[0], y = g[1], z = g[2];
        nx2[k] = pack2(-x, -x);
        ny2[k] = pack2(-y, -y);
        nz2[k] = pack2(-z, -z);
        qs[k]  = x * x + y * y + z * z;
        mA[k]  = 3.4e38f;
        mB[k]  = 3.4e38f;
    }
    __syncthreads();

    const ulonglong2* __restrict__ pxy = reinterpret_cast<const ulonglong2*>(sxy);
    const ulonglong2* __restrict__ pzc = reinterpret_cast<const ulonglong2*>(szc);

#pragma unroll 4
    for (int jp = 0; jp < JPAIRS; jp++) {
        ulonglong2 vxy = pxy[jp];   // {x0,x1},{y0,y1}  (LDS.128 broadcast)
        ulonglong2 vzc = pzc[jp];   // {z0,z1},{c0,c1}
#pragma unroll
        for (int k = 0; k < ITILE; k++) {
            u64 h2 = fma2(nz2[k], vzc.x, vzc.y);
            h2 = fma2(ny2[k], vxy.y, h2);
            h2 = fma2(nx2[k], vxy.x, h2);
            float h0, h1; unpack2(h2, h0, h1);
            mA[k] = fminf(mA[k], h0);
            mB[k] = fminf(mB[k], h1);
        }
    }

    float* out = g_partial + ((size_t)bz * JCHUNKS + chunk) * NPTS;
#pragma unroll
    for (int k = 0; k < ITILE; k++) {
        float m  = fminf(mA[k], mB[k]);
        float sq = fmaxf(fmaf(2.0f, m, qs[k]), 0.0f);  // clamp commutes with min
        out[q0 + k * THREADS] = sq;
    }
}

// Stage 1: min over chunks, sqrt, per-block sum. 64 blocks x 256 threads,
// 2 queries/thread covers 2*BATCH*NPTS = 32768 query slots.
__global__ __launch_bounds__(THREADS)
void chamfer_reduce_a() {
    __shared__ float ssum[THREADS];
    float acc = 0.0f;
#pragma unroll
    for (int r = 0; r < 2; r++) {
        int f  = blockIdx.x * 512 + r * THREADS + threadIdx.x;  // 0..32767
        int db = f / NPTS;
        int q  = f % NPTS;
        const float* p = g_partial + (size_t)db * JCHUNKS * NPTS + q;
        float mv = 3.4e38f;
#pragma unroll
        for (int c = 0; c < JCHUNKS; c++) mv = fminf(mv, p[(size_t)c * NPTS]);
        acc += sqrtf(mv);
    }
    ssum[threadIdx.x] = acc;
    __syncthreads();
    for (int s = THREADS / 2; s > 0; s >>= 1) {
        if (threadIdx.x < s) ssum[threadIdx.x] += ssum[threadIdx.x + s];
        __syncthreads();
    }
    if (threadIdx.x == 0) g_blocksum[blockIdx.x] = ssum[0];
}

// Stage 2: final deterministic sum of the 64 block sums.
__global__ void chamfer_reduce_b(float* __restrict__ out) {
    __shared__ float s[64];
    s[threadIdx.x] = g_blocksum[threadIdx.x];
    __syncthreads();
    for (int st = 32; st > 0; st >>= 1) {
        if (threadIdx.x < st) s[threadIdx.x] += s[threadIdx.x + st];
        __syncthreads();
    }
    if (threadIdx.x == 0) out[0] = s[0] / (float)(BATCH * NPTS);
}

extern "C" void kernel_launch(void* const* d_in, const int* in_sizes, int n_in,
                              void* d_out, int out_size) {
    const float* pred = (const float*)d_in[0];
    const float* gt   = (const float*)d_in[1];
    float* out        = (float*)d_out;

    dim3 grid(JCHUNKS, NQBLK, 2 * BATCH);   // 32 x 8 x 4 = 1024 CTAs
    chamfer_pass<<<grid, THREADS>>>(pred, gt);
    chamfer_reduce_a<<<64, THREADS>>>();
    chamfer_reduce_b<<<1, 64>>>(out);
}